// round 1
// baseline (speedup 1.0000x reference)
#include <cuda_runtime.h>

// Problem constants
#define B_  4
#define S_  1024
#define H_  16
#define D_  64
#define E_  1024
#define P_  1024
#define NS_ 2048   // P + S

// Scratch (no allocations allowed -> device globals)
__device__ float g_Qh[B_ * H_ * S_ * D_];     // Q in [B,H,S,D] layout, 16 MB
__device__ float g_attn[B_ * S_ * E_];        // attention output [B,S,E], 16 MB

// ---------------------------------------------------------------------------
// Copy layer_past [2,B,H,P,D] into the first half of present [2,B,H,NS,D]
// ---------------------------------------------------------------------------
__global__ __launch_bounds__(256) void copy_past_kernel(const float* __restrict__ past,
                                                        float* __restrict__ present)
{
    int cbh = blockIdx.x;  // 0..127  (2*B*H chunks)
    const float4* src = (const float4*)(past + (size_t)cbh * (P_ * D_));
    float4* dst = (float4*)(present + (size_t)cbh * (NS_ * D_));
    for (int i = threadIdx.x; i < (P_ * D_) / 4; i += 256)
        dst[i] = src[i];
}

// ---------------------------------------------------------------------------
// QKV GEMM: [4096,1024] @ [1024,3072] + bias
// Epilogue routes: q -> g_Qh [B,H,S,D]; k,v -> present at seq offset P
// ---------------------------------------------------------------------------
__global__ __launch_bounds__(256) void qkv_gemm_kernel(const float* __restrict__ X,
                                                       const float* __restrict__ W,
                                                       const float* __restrict__ bias,
                                                       float* __restrict__ present)
{
    __shared__ __align__(16) float As[8][128];
    __shared__ __align__(16) float Bs[8][128];
    const int K = 1024, N = 3072;
    int tid = threadIdx.x;
    int bm = blockIdx.y * 128, bn = blockIdx.x * 128;
    int arow = tid >> 1, acol = (tid & 1) * 4;
    int brow = tid >> 5, bcol = (tid & 31) * 4;
    int ty = tid >> 4, tx = tid & 15;

    float acc[8][8];
#pragma unroll
    for (int i = 0; i < 8; i++)
#pragma unroll
        for (int j = 0; j < 8; j++) acc[i][j] = 0.f;

    for (int k0 = 0; k0 < K; k0 += 8) {
        float4 av = *(const float4*)(X + (size_t)(bm + arow) * K + k0 + acol);
        float4 bv = *(const float4*)(W + (size_t)(k0 + brow) * N + bn + bcol);
        __syncthreads();
        As[acol + 0][arow] = av.x;
        As[acol + 1][arow] = av.y;
        As[acol + 2][arow] = av.z;
        As[acol + 3][arow] = av.w;
        *(float4*)&Bs[brow][bcol] = bv;
        __syncthreads();
#pragma unroll
        for (int kk = 0; kk < 8; kk++) {
            float4 a[2], b[2];
            a[0] = *(const float4*)&As[kk][ty * 8];
            a[1] = *(const float4*)&As[kk][ty * 8 + 4];
            b[0] = *(const float4*)&Bs[kk][tx * 8];
            b[1] = *(const float4*)&Bs[kk][tx * 8 + 4];
            const float* af = (const float*)a;
            const float* bf = (const float*)b;
#pragma unroll
            for (int i = 0; i < 8; i++)
#pragma unroll
                for (int j = 0; j < 8; j++)
                    acc[i][j] += af[i] * bf[j];
        }
    }

#pragma unroll
    for (int i = 0; i < 8; i++) {
        int mrow = bm + ty * 8 + i;
        int b = mrow >> 10, s = mrow & 1023;
#pragma unroll
        for (int j = 0; j < 8; j++) {
            int n = bn + tx * 8 + j;
            float v = acc[i][j] + bias[n];
            int part = n >> 10;      // 0=q, 1=k, 2=v
            int nn = n & 1023;
            int h = nn >> 6, d = nn & 63;
            if (part == 0) {
                g_Qh[(((b * H_ + h) * S_) + s) * D_ + d] = v;
            } else if (part == 1) {
                present[(((size_t)(b * H_ + h)) * NS_ + P_ + s) * D_ + d] = v;
            } else {
                present[(((size_t)((B_ + b) * H_ + h)) * NS_ + P_ + s) * D_ + d] = v;
            }
        }
    }
}

// ---------------------------------------------------------------------------
// Flash attention: one thread per query row. Block = (128 queries) x (b,h).
// K/V tiles (64x64) staged in smem; scores & PV via float4 broadcast LDS.
// ---------------------------------------------------------------------------
__global__ __launch_bounds__(128) void attn_kernel(const float* __restrict__ present)
{
    __shared__ __align__(16) float Ks[64][64];
    __shared__ __align__(16) float Vs[64][64];

    int bh = blockIdx.y;               // 0..63
    int b = bh >> 4, h = bh & 15;
    int q0 = blockIdx.x * 128;
    int tid = threadIdx.x;
    int s = q0 + tid;                  // query position

    const float* Kb = present + (size_t)bh * (NS_ * D_);
    const float* Vb = present + (size_t)(B_ * H_ + bh) * (NS_ * D_);

    float4 q4[16], o4[16];
    const float* qp = g_Qh + ((size_t)bh * S_ + s) * D_;
#pragma unroll
    for (int i = 0; i < 16; i++) {
        float4 t = *(const float4*)(qp + i * 4);
        t.x *= 0.125f; t.y *= 0.125f; t.z *= 0.125f; t.w *= 0.125f;  // 1/sqrt(64)
        q4[i] = t;
        o4[i] = make_float4(0.f, 0.f, 0.f, 0.f);
    }
    float m = -1e30f, l = 0.f;

    int kend = P_ + q0 + 128;          // exclusive; multiple of 64
    for (int j0 = 0; j0 < kend; j0 += 64) {
        __syncthreads();
        for (int t = tid; t < 64 * 16; t += 128) {
            int r = t >> 4, c = (t & 15) << 2;
            *(float4*)&Ks[r][c] = *(const float4*)(Kb + (size_t)(j0 + r) * D_ + c);
            *(float4*)&Vs[r][c] = *(const float4*)(Vb + (size_t)(j0 + r) * D_ + c);
        }
        __syncthreads();

        int limit = P_ + s - j0;       // key j in tile allowed iff j <= limit
#pragma unroll 1
        for (int jj = 0; jj < 64; jj += 8) {
            float sc[8];
#pragma unroll
            for (int j = 0; j < 8; j++) {
                float acc = 0.f;
#pragma unroll
                for (int dd = 0; dd < 16; dd++) {
                    float4 kv = *(const float4*)&Ks[jj + j][dd * 4];
                    acc += q4[dd].x * kv.x + q4[dd].y * kv.y +
                           q4[dd].z * kv.z + q4[dd].w * kv.w;
                }
                sc[j] = (jj + j <= limit) ? acc : -1e30f;
            }
            float tm = m;
#pragma unroll
            for (int j = 0; j < 8; j++) tm = fmaxf(tm, sc[j]);
            float alpha = __expf(m - tm);
            m = tm;
            l *= alpha;
            float p[8];
#pragma unroll
            for (int j = 0; j < 8; j++) { p[j] = __expf(sc[j] - m); l += p[j]; }
#pragma unroll
            for (int dd = 0; dd < 16; dd++) {
                float4 a = o4[dd];
                a.x *= alpha; a.y *= alpha; a.z *= alpha; a.w *= alpha;
#pragma unroll
                for (int j = 0; j < 8; j++) {
                    float4 vv = *(const float4*)&Vs[jj + j][dd * 4];
                    a.x += p[j] * vv.x; a.y += p[j] * vv.y;
                    a.z += p[j] * vv.z; a.w += p[j] * vv.w;
                }
                o4[dd] = a;
            }
        }
    }

    float invl = 1.f / l;
    float* dst = g_attn + ((size_t)(b * S_ + s)) * E_ + h * D_;
#pragma unroll
    for (int dd = 0; dd < 16; dd++) {
        float4 a = o4[dd];
        a.x *= invl; a.y *= invl; a.z *= invl; a.w *= invl;
        *(float4*)(dst + dd * 4) = a;
    }
}

// ---------------------------------------------------------------------------
// Output projection: [4096,1024] @ [1024,1024] + bias -> out
// ---------------------------------------------------------------------------
__global__ __launch_bounds__(256) void proj_gemm_kernel(const float* __restrict__ W,
                                                        const float* __restrict__ bias,
                                                        float* __restrict__ out)
{
    __shared__ __align__(16) float As[8][128];
    __shared__ __align__(16) float Bs[8][128];
    const int K = 1024, N = 1024;
    int tid = threadIdx.x;
    int bm = blockIdx.y * 128, bn = blockIdx.x * 128;
    int arow = tid >> 1, acol = (tid & 1) * 4;
    int brow = tid >> 5, bcol = (tid & 31) * 4;
    int ty = tid >> 4, tx = tid & 15;

    float acc[8][8];
#pragma unroll
    for (int i = 0; i < 8; i++)
#pragma unroll
        for (int j = 0; j < 8; j++) acc[i][j] = 0.f;

    for (int k0 = 0; k0 < K; k0 += 8) {
        float4 av = *(const float4*)(g_attn + (size_t)(bm + arow) * K + k0 + acol);
        float4 bv = *(const float4*)(W + (size_t)(k0 + brow) * N + bn + bcol);
        __syncthreads();
        As[acol + 0][arow] = av.x;
        As[acol + 1][arow] = av.y;
        As[acol + 2][arow] = av.z;
        As[acol + 3][arow] = av.w;
        *(float4*)&Bs[brow][bcol] = bv;
        __syncthreads();
#pragma unroll
        for (int kk = 0; kk < 8; kk++) {
            float4 a[2], b[2];
            a[0] = *(const float4*)&As[kk][ty * 8];
            a[1] = *(const float4*)&As[kk][ty * 8 + 4];
            b[0] = *(const float4*)&Bs[kk][tx * 8];
            b[1] = *(const float4*)&Bs[kk][tx * 8 + 4];
            const float* af = (const float*)a;
            const float* bf = (const float*)b;
#pragma unroll
            for (int i = 0; i < 8; i++)
#pragma unroll
                for (int j = 0; j < 8; j++)
                    acc[i][j] += af[i] * bf[j];
        }
    }

#pragma unroll
    for (int i = 0; i < 8; i++) {
        int mrow = bm + ty * 8 + i;
#pragma unroll
        for (int j = 0; j < 8; j++) {
            int n = bn + tx * 8 + j;
            out[(size_t)mrow * N + n] = acc[i][j] + bias[n];
        }
    }
}

// ---------------------------------------------------------------------------
extern "C" void kernel_launch(void* const* d_in, const int* in_sizes, int n_in,
                              void* d_out, int out_size)
{
    (void)in_sizes; (void)n_in; (void)out_size;
    const float* x      = (const float*)d_in[0];   // [B,S,E]
    const float* past   = (const float*)d_in[1];   // [2,B,H,P,D]
    const float* w_attn = (const float*)d_in[2];   // [E,3E]
    const float* b_attn = (const float*)d_in[3];   // [3E]
    const float* w_proj = (const float*)d_in[4];   // [E,E]
    const float* b_proj = (const float*)d_in[5];   // [E]

    float* out     = (float*)d_out;                          // [B,S,E]
    float* present = out + (size_t)B_ * S_ * E_;             // [2,B,H,NS,D]

    copy_past_kernel<<<2 * B_ * H_, 256>>>(past, present);
    qkv_gemm_kernel<<<dim3(3 * E_ / 128, (B_ * S_) / 128), 256>>>(x, w_attn, b_attn, present);
    attn_kernel<<<dim3(S_ / 128, B_ * H_), 128>>>(present);
    proj_gemm_kernel<<<dim3(E_ / 128, (B_ * S_) / 128), 256>>>(w_proj, b_proj, out);
}

// round 4
// speedup vs baseline: 3.9748x; 3.9748x over previous
#include <cuda_runtime.h>
#include <cuda_bf16.h>

#define B_  4
#define S_  1024
#define H_  16
#define D_  64
#define E_  1024
#define P_  1024
#define NS_ 2048
#define K_  1024

__device__ float g_Qh[B_ * H_ * S_ * D_];     // Q in [B,H,S,D]
__device__ float g_attn[B_ * S_ * E_];        // attention out [B,S,E]

// ---------------- helpers ----------------
__device__ __forceinline__ unsigned f2tf32(float x) {
    unsigned r; asm("cvt.rna.tf32.f32 %0, %1;" : "=r"(r) : "f"(x)); return r;
}
__device__ __forceinline__ float ex2f(float x) {
    float r; asm("ex2.approx.ftz.f32 %0, %1;" : "=f"(r) : "f"(x)); return r;
}
__device__ __forceinline__ void mma_tf32(float* d, const unsigned* a, const unsigned* b) {
    asm volatile("mma.sync.aligned.m16n8k8.row.col.f32.tf32.tf32.f32 "
        "{%0,%1,%2,%3}, {%4,%5,%6,%7}, {%8,%9}, {%0,%1,%2,%3};"
        : "+f"(d[0]), "+f"(d[1]), "+f"(d[2]), "+f"(d[3])
        : "r"(a[0]), "r"(a[1]), "r"(a[2]), "r"(a[3]), "r"(b[0]), "r"(b[1]));
}

// ---------------- copy past -> present ----------------
__global__ __launch_bounds__(256) void copy_past_kernel(const float* __restrict__ past,
                                                        float* __restrict__ present)
{
    int blk = blockIdx.x;            // 512 blocks: cbh(128) x quarter(4)
    int cbh = blk >> 2, qtr = blk & 3;
    const float4* src = (const float4*)(past + (size_t)cbh * (P_ * D_) + qtr * (P_ * D_ / 4));
    float4* dst = (float4*)(present + (size_t)cbh * (NS_ * D_) + qtr * (P_ * D_ / 4));
    for (int i = threadIdx.x; i < (P_ * D_ / 4) / 4; i += 256)
        dst[i] = src[i];
}

// ---------------- tf32 GEMM: C[M=4096, N] = A[M,1024] @ B[1024,N] + bias ----
// qkv_mode=1: route q->g_Qh, k/v->present ; qkv_mode=0: A=g_attn, store Cout
__global__ __launch_bounds__(256) void gemm_tf32_kernel(
    const float* __restrict__ Ain, const float* __restrict__ Bw,
    const float* __restrict__ bias, float* __restrict__ Cout,
    float* __restrict__ present, int N, int qkv_mode)
{
    const float* A = qkv_mode ? Ain : (const float*)g_attn;  // device-side symbol ref

    __shared__ unsigned As[2][16][136];
    __shared__ unsigned Bs[2][16][136];

    int t = threadIdx.x;
    int bm = blockIdx.y * 128, bn = blockIdx.x * 128;
    int w = t >> 5, l = t & 31;
    int wm = (w & 1) * 64, wn = (w >> 1) * 32;
    int r = l >> 2, c = l & 3;

    // global load mapping
    int ar = t >> 2, ac = (t & 3) * 4;      // A: rows ar, ar+64 ; k-cols ac..ac+3
    int bkr = t >> 4, bcg = (t & 15) * 4;   // B: k-row bkr ; cols bcg, bcg+64

    float acc[4][4][4];
#pragma unroll
    for (int i = 0; i < 4; i++)
#pragma unroll
        for (int j = 0; j < 4; j++)
#pragma unroll
            for (int k = 0; k < 4; k++) acc[i][j][k] = 0.f;

    const float* Ap = A + (size_t)(bm + ar) * K_ + ac;
    const float* Bp = Bw + (size_t)bkr * N + bn + bcg;

    float4 pa0 = *(const float4*)(Ap);
    float4 pa1 = *(const float4*)(Ap + (size_t)64 * K_);
    float4 pb0 = *(const float4*)(Bp);
    float4 pb1 = *(const float4*)(Bp + 64);

    int buf = 0;
    for (int k0 = 0; k0 < K_; k0 += 16) {
        As[buf][ac + 0][ar] = f2tf32(pa0.x);
        As[buf][ac + 1][ar] = f2tf32(pa0.y);
        As[buf][ac + 2][ar] = f2tf32(pa0.z);
        As[buf][ac + 3][ar] = f2tf32(pa0.w);
        As[buf][ac + 0][ar + 64] = f2tf32(pa1.x);
        As[buf][ac + 1][ar + 64] = f2tf32(pa1.y);
        As[buf][ac + 2][ar + 64] = f2tf32(pa1.z);
        As[buf][ac + 3][ar + 64] = f2tf32(pa1.w);
        {
            uint4 u0 = make_uint4(f2tf32(pb0.x), f2tf32(pb0.y), f2tf32(pb0.z), f2tf32(pb0.w));
            uint4 u1 = make_uint4(f2tf32(pb1.x), f2tf32(pb1.y), f2tf32(pb1.z), f2tf32(pb1.w));
            *(uint4*)&Bs[buf][bkr][bcg] = u0;
            *(uint4*)&Bs[buf][bkr][bcg + 64] = u1;
        }
        __syncthreads();

        if (k0 + 16 < K_) {
            pa0 = *(const float4*)(Ap + k0 + 16);
            pa1 = *(const float4*)(Ap + (size_t)64 * K_ + k0 + 16);
            pb0 = *(const float4*)(Bp + (size_t)(k0 + 16) * N);
            pb1 = *(const float4*)(Bp + (size_t)(k0 + 16) * N + 64);
        }

#pragma unroll
        for (int kk = 0; kk < 16; kk += 8) {
            unsigned af[4][4], bf[4][2];
#pragma unroll
            for (int mi = 0; mi < 4; mi++) {
                int m0 = wm + mi * 16;
                af[mi][0] = As[buf][kk + c][m0 + r];
                af[mi][1] = As[buf][kk + c][m0 + r + 8];
                af[mi][2] = As[buf][kk + c + 4][m0 + r];
                af[mi][3] = As[buf][kk + c + 4][m0 + r + 8];
            }
#pragma unroll
            for (int ni = 0; ni < 4; ni++) {
                int n0 = wn + ni * 8;
                bf[ni][0] = Bs[buf][kk + c][n0 + r];
                bf[ni][1] = Bs[buf][kk + c + 4][n0 + r];
            }
#pragma unroll
            for (int mi = 0; mi < 4; mi++)
#pragma unroll
                for (int ni = 0; ni < 4; ni++)
                    mma_tf32(acc[mi][ni], af[mi], bf[ni]);
        }
        buf ^= 1;
        __syncthreads();
    }

    // epilogue
#pragma unroll
    for (int mi = 0; mi < 4; mi++) {
#pragma unroll
        for (int ni = 0; ni < 4; ni++) {
            int row0 = bm + wm + mi * 16 + r;
            int col = bn + wn + ni * 8 + 2 * c;
#pragma unroll
            for (int jj = 0; jj < 4; jj++) {
                int row = (jj < 2) ? row0 : row0 + 8;
                int cg = col + (jj & 1);
                float v = acc[mi][ni][jj] + bias[cg];
                if (!qkv_mode) {
                    Cout[(size_t)row * N + cg] = v;
                } else {
                    int b = row >> 10, s = row & 1023;
                    int part = cg >> 10, nn = cg & 1023;
                    int h = nn >> 6, d = nn & 63;
                    if (part == 0)
                        g_Qh[(((b * H_ + h) * S_) + s) * D_ + d] = v;
                    else if (part == 1)
                        present[(((size_t)(b * H_ + h)) * NS_ + P_ + s) * D_ + d] = v;
                    else
                        present[(((size_t)((B_ + b) * H_ + h)) * NS_ + P_ + s) * D_ + d] = v;
                }
            }
        }
    }
}

// ---------------- tensor-core flash attention (all-tf32) ----------------
// CTA: 128 q-rows x (b,h). 8 warps, warp w owns rows [16w,16w+16).
// scores: tf32 mma (Q regs x K smem). PV: tf32 mma, P repacked via shfl.
__global__ __launch_bounds__(256) void attn_mma_kernel(const float* __restrict__ present)
{
    __shared__ unsigned Ks[64][68];          // tf32 bits, [key][d]
    __shared__ unsigned Vt[64][68];          // tf32 bits, [d][key] transposed

    int t = threadIdx.x, w = t >> 5, l = t & 31;
    int r = l >> 2, c = l & 3;
    int bh = blockIdx.y, q0 = blockIdx.x * 128;
    int b = bh >> 4, h = bh & 15;

    const float* Kb = present + (size_t)bh * (NS_ * D_);
    const float* Vb = present + (size_t)(B_ * H_ + bh) * (NS_ * D_);

    // Q fragments, prescaled by 1/sqrt(64) * log2(e)
    const float SC = 0.125f * 1.4426950408889634f;
    unsigned qf[8][4];
    {
        const float* Qp = g_Qh + ((size_t)bh * S_ + q0 + w * 16) * D_;
#pragma unroll
        for (int ks = 0; ks < 8; ks++) {
            int kc = ks * 8;
            qf[ks][0] = f2tf32(SC * Qp[(size_t)r * D_ + kc + c]);
            qf[ks][1] = f2tf32(SC * Qp[(size_t)(r + 8) * D_ + kc + c]);
            qf[ks][2] = f2tf32(SC * Qp[(size_t)r * D_ + kc + c + 4]);
            qf[ks][3] = f2tf32(SC * Qp[(size_t)(r + 8) * D_ + kc + c + 4]);
        }
    }

    float o[8][4];
#pragma unroll
    for (int i = 0; i < 8; i++)
#pragma unroll
        for (int j = 0; j < 4; j++) o[i][j] = 0.f;
    const float NEG = __int_as_float(0xff800000);
    float m0 = NEG, m1 = NEG, l0 = 0.f, l1 = 0.f;

    int key = t >> 2, cb = (t & 3) * 4;      // staging: rows=key, col groups cb+16i
    float4 pk[4], pv[4];
#pragma unroll
    for (int i = 0; i < 4; i++) {
        pk[i] = *(const float4*)(Kb + (size_t)key * D_ + cb + 16 * i);
        pv[i] = *(const float4*)(Vb + (size_t)key * D_ + cb + 16 * i);
    }

    // shuffle source lanes for P repack (A-frag needs key-cols c and c+4)
    int lsrc0 = (l & ~3) | (c >> 1);
    int lsrc1 = lsrc0 + 2;
    bool sel = (c & 1);

    int ntiles = (P_ + q0 + 128) / 64;
    for (int it = 0; it < ntiles; ++it) {
        int j0 = it * 64;
        // stage tiles
#pragma unroll
        for (int i = 0; i < 4; i++) {
            int cc = cb + 16 * i;
            Ks[key][cc + 0] = f2tf32(pk[i].x);
            Ks[key][cc + 1] = f2tf32(pk[i].y);
            Ks[key][cc + 2] = f2tf32(pk[i].z);
            Ks[key][cc + 3] = f2tf32(pk[i].w);
            Vt[cc + 0][key] = f2tf32(pv[i].x);
            Vt[cc + 1][key] = f2tf32(pv[i].y);
            Vt[cc + 2][key] = f2tf32(pv[i].z);
            Vt[cc + 3][key] = f2tf32(pv[i].w);
        }
        __syncthreads();

        if (it + 1 < ntiles) {
            int jn = j0 + 64;
#pragma unroll
            for (int i = 0; i < 4; i++) {
                pk[i] = *(const float4*)(Kb + (size_t)(jn + key) * D_ + cb + 16 * i);
                pv[i] = *(const float4*)(Vb + (size_t)(jn + key) * D_ + cb + 16 * i);
            }
        }

        // scores: s[nt] = 16x8 tile over keys j0+8nt..+7
        float s[8][4];
#pragma unroll
        for (int nt = 0; nt < 8; nt++) {
            s[nt][0] = s[nt][1] = s[nt][2] = s[nt][3] = 0.f;
#pragma unroll
            for (int ks = 0; ks < 8; ks++) {
                unsigned bf[2] = { Ks[nt * 8 + r][ks * 8 + c], Ks[nt * 8 + r][ks * 8 + c + 4] };
                mma_tf32(s[nt], qf[ks], bf);
            }
        }

        // causal mask
        int qrow = q0 + w * 16 + r;
        int lim0 = P_ + qrow - j0;       // key col allowed iff <= lim
        int lim1 = lim0 + 8;
#pragma unroll
        for (int nt = 0; nt < 8; nt++) {
            int j = nt * 8 + 2 * c;
            if (j > lim0) s[nt][0] = NEG;
            if (j + 1 > lim0) s[nt][1] = NEG;
            if (j > lim1) s[nt][2] = NEG;
            if (j + 1 > lim1) s[nt][3] = NEG;
        }

        // online softmax (base-2 domain)
        float mx0 = NEG, mx1 = NEG;
#pragma unroll
        for (int nt = 0; nt < 8; nt++) {
            mx0 = fmaxf(mx0, fmaxf(s[nt][0], s[nt][1]));
            mx1 = fmaxf(mx1, fmaxf(s[nt][2], s[nt][3]));
        }
        mx0 = fmaxf(mx0, __shfl_xor_sync(0xffffffffu, mx0, 1));
        mx0 = fmaxf(mx0, __shfl_xor_sync(0xffffffffu, mx0, 2));
        mx1 = fmaxf(mx1, __shfl_xor_sync(0xffffffffu, mx1, 1));
        mx1 = fmaxf(mx1, __shfl_xor_sync(0xffffffffu, mx1, 2));
        float nm0 = fmaxf(m0, mx0), nm1 = fmaxf(m1, mx1);
        float a0 = ex2f(m0 - nm0), a1 = ex2f(m1 - nm1);
        m0 = nm0; m1 = nm1;
        l0 *= a0; l1 *= a1;
#pragma unroll
        for (int nt = 0; nt < 8; nt++) {
            s[nt][0] = ex2f(s[nt][0] - nm0);
            s[nt][1] = ex2f(s[nt][1] - nm0);
            s[nt][2] = ex2f(s[nt][2] - nm1);
            s[nt][3] = ex2f(s[nt][3] - nm1);
            l0 += s[nt][0] + s[nt][1];
            l1 += s[nt][2] + s[nt][3];
            o[nt][0] *= a0; o[nt][1] *= a0;
            o[nt][2] *= a1; o[nt][3] *= a1;
        }

        // PV: o += P(tf32) @ V(tf32); P fragment via in-warp shuffle repack
#pragma unroll
        for (int ks = 0; ks < 8; ks++) {
            unsigned p0 = f2tf32(s[ks][0]), p1 = f2tf32(s[ks][1]);
            unsigned p2 = f2tf32(s[ks][2]), p3 = f2tf32(s[ks][3]);
            unsigned u0 = __shfl_sync(0xffffffffu, p0, lsrc0);
            unsigned u1 = __shfl_sync(0xffffffffu, p1, lsrc0);
            unsigned u2 = __shfl_sync(0xffffffffu, p2, lsrc0);
            unsigned u3 = __shfl_sync(0xffffffffu, p3, lsrc0);
            unsigned v0 = __shfl_sync(0xffffffffu, p0, lsrc1);
            unsigned v1 = __shfl_sync(0xffffffffu, p1, lsrc1);
            unsigned v2 = __shfl_sync(0xffffffffu, p2, lsrc1);
            unsigned v3 = __shfl_sync(0xffffffffu, p3, lsrc1);
            unsigned ap[4];
            ap[0] = sel ? u1 : u0;       // P(r,   ks*8+c)
            ap[1] = sel ? u3 : u2;       // P(r+8, ks*8+c)
            ap[2] = sel ? v1 : v0;       // P(r,   ks*8+c+4)
            ap[3] = sel ? v3 : v2;       // P(r+8, ks*8+c+4)
#pragma unroll
            for (int nt = 0; nt < 8; nt++) {
                unsigned bf[2] = { Vt[nt * 8 + r][ks * 8 + c], Vt[nt * 8 + r][ks * 8 + c + 4] };
                mma_tf32(o[nt], ap, bf);
            }
        }
        __syncthreads();
    }

    // finalize
    l0 += __shfl_xor_sync(0xffffffffu, l0, 1);
    l0 += __shfl_xor_sync(0xffffffffu, l0, 2);
    l1 += __shfl_xor_sync(0xffffffffu, l1, 1);
    l1 += __shfl_xor_sync(0xffffffffu, l1, 2);
    float inv0 = 1.f / l0, inv1 = 1.f / l1;

    int qrow = q0 + w * 16 + r;
    float* dst0 = g_attn + ((size_t)(b * S_ + qrow)) * E_ + h * D_;
    float* dst1 = dst0 + (size_t)8 * E_;
#pragma unroll
    for (int nt = 0; nt < 8; nt++) {
        int cc = nt * 8 + 2 * c;
        *(float2*)(dst0 + cc) = make_float2(o[nt][0] * inv0, o[nt][1] * inv0);
        *(float2*)(dst1 + cc) = make_float2(o[nt][2] * inv1, o[nt][3] * inv1);
    }
}

// ---------------------------------------------------------------------------
extern "C" void kernel_launch(void* const* d_in, const int* in_sizes, int n_in,
                              void* d_out, int out_size)
{
    (void)in_sizes; (void)n_in; (void)out_size;
    const float* x      = (const float*)d_in[0];
    const float* past   = (const float*)d_in[1];
    const float* w_attn = (const float*)d_in[2];
    const float* b_attn = (const float*)d_in[3];
    const float* w_proj = (const float*)d_in[4];
    const float* b_proj = (const float*)d_in[5];

    float* out     = (float*)d_out;
    float* present = out + (size_t)B_ * S_ * E_;

    copy_past_kernel<<<512, 256>>>(past, present);
    gemm_tf32_kernel<<<dim3(3 * E_ / 128, (B_ * S_) / 128), 256>>>(
        x, w_attn, b_attn, nullptr, present, 3 * E_, 1);
    attn_mma_kernel<<<dim3(S_ / 128, B_ * H_), 256>>>(present);
    gemm_tf32_kernel<<<dim3(E_ / 128, (B_ * S_) / 128), 256>>>(
        nullptr, w_proj, b_proj, out, nullptr, E_, 0);
}